// round 17
// baseline (speedup 1.0000x reference)
#include <cuda_runtime.h>
#include <cuda_bf16.h>

// Segment-mean over sorted segment_ids, two-kernel plan:
//  K1 build_starts_vec4: int4-vectorized boundary scan -> starts[S+1] (~2us).
//  K2 segmean: one CTA per segment, 4 warps x float4 columns, manually
//     8-deep pipelined __ldcs stream. R9 post-mortem showed outstanding-load
//     depth (not DRAM efficiency) was the binding constraint: 4-deep manual
//     batching took DRAM 80->89%. 8-deep trades occupancy (16->10 CTAs/SM)
//     for +25% in-flight bytes. __stcs output stores.

#define MAX_SEGMENTS (1 << 22)
__device__ int g_starts[MAX_SEGMENTS + 1];

__global__ void build_starts_vec4(const int* __restrict__ seg, int N, int S,
                                  int* __restrict__ starts) {
    const int t  = blockIdx.x * blockDim.x + threadIdx.x;
    const int e0 = t * 4;
    if (e0 >= N) return;

    int v0, v1, v2, v3;
    if (e0 + 3 < N) {
        int4 v = __ldg((const int4*)(seg + e0));
        v0 = v.x; v1 = v.y; v2 = v.z; v3 = v.w;
    } else {
        v0 = __ldg(seg + e0);
        v1 = (e0 + 1 < N) ? __ldg(seg + e0 + 1) : v0;
        v2 = (e0 + 2 < N) ? __ldg(seg + e0 + 2) : v1;
        v3 = (e0 + 3 < N) ? __ldg(seg + e0 + 3) : v2;
    }

    if (e0 == 0) {
        for (int s = 0; s <= v0; ++s) starts[s] = 0;
    } else {
        int pv = __ldg(seg + e0 - 1);
        if (pv != v0) for (int s = pv + 1; s <= v0; ++s) starts[s] = e0;
    }
    if (e0 + 1 < N && v0 != v1) for (int s = v0 + 1; s <= v1; ++s) starts[s] = e0 + 1;
    if (e0 + 2 < N && v1 != v2) for (int s = v1 + 1; s <= v2; ++s) starts[s] = e0 + 2;
    if (e0 + 3 < N && v2 != v3) for (int s = v2 + 1; s <= v3; ++s) starts[s] = e0 + 3;

    if (e0 <= N - 1 && N - 1 < e0 + 4) {
        int last = (N - 1 == e0) ? v0 : (N - 1 == e0 + 1) ? v1
                 : (N - 1 == e0 + 2) ? v2 : v3;
        for (int s = last + 1; s <= S; ++s) starts[s] = N;
    }
}

__global__ void __launch_bounds__(128, 10)
segmean_kernel(const float4* __restrict__ feats4,   // [N, D/4]
               const int* __restrict__ starts,       // [S+1]
               int D4,                               // D/4 (=32)
               float4* __restrict__ out4)            // [S, D/4]
{
    const int s   = blockIdx.x;
    const int tid = threadIdx.x;

    const int start = __ldg(starts + s);
    const int end   = __ldg(starts + s + 1);
    const int count = end - start;

    const int step = blockDim.x / D4;         // 4 row-groups (one warp each)
    const int col  = tid % D4;
    const int rgrp = tid / D4;

    float4 acc = make_float4(0.f, 0.f, 0.f, 0.f);

    int r = start + rgrp;
    const long long colL = col;

    // Main loop: 8 rows per warp-iteration, all 8 LDG.128 issued before the
    // first FADD consumer -> 8 outstanding loads per thread.
    for (; r + 7 * step < end; r += 8 * step) {
        const float4* p = feats4 + (long long)r * D4 + colL;
        const long long st = (long long)step * D4;
        float4 a0 = __ldcs(p);
        float4 a1 = __ldcs(p + st);
        float4 a2 = __ldcs(p + 2 * st);
        float4 a3 = __ldcs(p + 3 * st);
        float4 a4 = __ldcs(p + 4 * st);
        float4 a5 = __ldcs(p + 5 * st);
        float4 a6 = __ldcs(p + 6 * st);
        float4 a7 = __ldcs(p + 7 * st);
        acc.x += a0.x; acc.y += a0.y; acc.z += a0.z; acc.w += a0.w;
        acc.x += a1.x; acc.y += a1.y; acc.z += a1.z; acc.w += a1.w;
        acc.x += a2.x; acc.y += a2.y; acc.z += a2.z; acc.w += a2.w;
        acc.x += a3.x; acc.y += a3.y; acc.z += a3.z; acc.w += a3.w;
        acc.x += a4.x; acc.y += a4.y; acc.z += a4.z; acc.w += a4.w;
        acc.x += a5.x; acc.y += a5.y; acc.z += a5.z; acc.w += a5.w;
        acc.x += a6.x; acc.y += a6.y; acc.z += a6.z; acc.w += a6.w;
        acc.x += a7.x; acc.y += a7.y; acc.z += a7.z; acc.w += a7.w;
    }
    // 4-deep mid tail
    for (; r + 3 * step < end; r += 4 * step) {
        const float4* p = feats4 + (long long)r * D4 + colL;
        const long long st = (long long)step * D4;
        float4 a0 = __ldcs(p);
        float4 a1 = __ldcs(p + st);
        float4 a2 = __ldcs(p + 2 * st);
        float4 a3 = __ldcs(p + 3 * st);
        acc.x += a0.x; acc.y += a0.y; acc.z += a0.z; acc.w += a0.w;
        acc.x += a1.x; acc.y += a1.y; acc.z += a1.z; acc.w += a1.w;
        acc.x += a2.x; acc.y += a2.y; acc.z += a2.z; acc.w += a2.w;
        acc.x += a3.x; acc.y += a3.y; acc.z += a3.z; acc.w += a3.w;
    }
    // Scalar tail
    for (; r < end; r += step) {
        float4 v = __ldcs(feats4 + (long long)r * D4 + colL);
        acc.x += v.x; acc.y += v.y; acc.z += v.z; acc.w += v.w;
    }

    __shared__ float4 sh[128];
    sh[tid] = acc;
    __syncthreads();

    if (rgrp == 0) {
        float4 a = sh[col];
        #pragma unroll
        for (int g = 1; g < 4; ++g) {
            float4 b = sh[g * D4 + col];
            a.x += b.x; a.y += b.y; a.z += b.z; a.w += b.w;
        }
        const float inv = 1.0f / (float)max(count, 1);
        a.x *= inv; a.y *= inv; a.z *= inv; a.w *= inv;
        __stcs(out4 + (long long)s * D4 + col, a);
    }
}

extern "C" void kernel_launch(void* const* d_in, const int* in_sizes, int n_in,
                              void* d_out, int out_size) {
    const float* feats = (const float*)d_in[0];
    const int*   seg   = (const int*)d_in[1];

    const int N  = in_sizes[1];
    const int D  = in_sizes[0] / N;      // 128
    const int D4 = D >> 2;
    const int S  = out_size / D;

    int* starts = nullptr;
    cudaGetSymbolAddress((void**)&starts, g_starts);

    const int quads = (N + 3) / 4;
    build_starts_vec4<<<(quads + 255) / 256, 256>>>(seg, N, S, starts);
    segmean_kernel<<<S, 128>>>((const float4*)feats, starts, D4, (float4*)d_out);
}